// round 16
// baseline (speedup 1.0000x reference)
#include <cuda_runtime.h>
#include <math.h>

// Problem constants
#define Bq   16
#define Nq   576
#define Cq   768
#define Hq   12
#define DHq  64
#define IMGq 24

// d_out layout (floats): out [B,N,C] | attn [B,H,N,N] | v [B,H,N,Dh]
#define OFF_ATTN 7077888
#define OFF_V    70778880

// Scratch (device globals; allocation-free rule). All *_t hold tf32-rounded fp32.
__device__ float g_xt[Bq * Nq * Cq];          // tf32(x)
__device__ float g_wqkt[Cq * 2 * Cq];         // tf32(w_qk)
__device__ float g_wvt[Cq * Cq];              // tf32(w_v)
__device__ float g_wpt[Cq * Cq];              // tf32(w_proj)
__device__ float g_q[Bq * Hq * Nq * DHq];     // tf32(q)  [B,H,N,Dh]
__device__ float g_k[Bq * Hq * Nq * DHq];     // tf32(k)
__device__ float g_ctx[Bq * Nq * Cq];         // tf32(ctx) [B,N,C]
__device__ float g_pos[Hq * Nq * Nq];         // fp32 positional probs [H,N,N]

// ---------------------------------------------------------------------------
__device__ __forceinline__ unsigned f2tf(float f) {
    unsigned u;
    asm("cvt.rna.tf32.f32 %0, %1;" : "=r"(u) : "f"(f));
    return u;
}
__device__ __forceinline__ float f2tff(float f) {
    return __uint_as_float(f2tf(f));
}

__device__ __forceinline__ void mma8(float* c,
                                     unsigned a0, unsigned a1, unsigned a2, unsigned a3,
                                     unsigned b0, unsigned b1)
{
    asm volatile(
        "mma.sync.aligned.m16n8k8.row.col.f32.tf32.tf32.f32 "
        "{%0,%1,%2,%3},{%4,%5,%6,%7},{%8,%9},{%0,%1,%2,%3};\n"
        : "+f"(c[0]), "+f"(c[1]), "+f"(c[2]), "+f"(c[3])
        : "r"(a0), "r"(a1), "r"(a2), "r"(a3), "r"(b0), "r"(b1));
}

__device__ __forceinline__ void cpasync16(void* smem_dst, const void* gmem_src) {
    unsigned s = (unsigned)__cvta_generic_to_shared(smem_dst);
    asm volatile("cp.async.cg.shared.global [%0], [%1], 16;\n" :: "r"(s), "l"(gmem_src));
}
#define CP_COMMIT() asm volatile("cp.async.commit_group;\n" ::: "memory")
#define CP_WAIT1()  asm volatile("cp.async.wait_group 1;\n" ::: "memory")
#define CP_WAIT0()  asm volatile("cp.async.wait_group 0;\n" ::: "memory")

// ---------------------------------------------------------------------------
// Elementwise tf32 rounding pre-pass (float4)
// ---------------------------------------------------------------------------
__global__ __launch_bounds__(256) void cvt_kernel(const float* __restrict__ src,
                                                  float* __restrict__ dst, int n4)
{
    int i = blockIdx.x * 256 + threadIdx.x;
    if (i < n4) {
        float4 v = ((const float4*)src)[i];
        float4 o;
        o.x = f2tff(v.x); o.y = f2tff(v.y); o.z = f2tff(v.z); o.w = f2tff(v.w);
        ((float4*)dst)[i] = o;
    }
}

// Dual-array variant (w_v and w_proj, equal sizes)
__global__ __launch_bounds__(256) void cvt2_kernel(const float* __restrict__ s0,
                                                   float* __restrict__ d0,
                                                   const float* __restrict__ s1,
                                                   float* __restrict__ d1, int n4)
{
    int i = blockIdx.x * 256 + threadIdx.x;
    if (i < n4) {
        float4 v = ((const float4*)s0)[i];
        float4 o;
        o.x = f2tff(v.x); o.y = f2tff(v.y); o.z = f2tff(v.z); o.w = f2tff(v.w);
        ((float4*)d0)[i] = o;
        v = ((const float4*)s1)[i];
        o.x = f2tff(v.x); o.y = f2tff(v.y); o.z = f2tff(v.z); o.w = f2tff(v.w);
        ((float4*)d1)[i] = o;
    }
}

// ---------------------------------------------------------------------------
// Positional scores: softmax over keys of analytic logits
// ---------------------------------------------------------------------------
__global__ __launch_bounds__(256) void pos_kernel(const float* __restrict__ wpos,
                                                  const float* __restrict__ bpos)
{
    int n = blockIdx.x;
    int h = blockIdx.y;
    int t = threadIdx.x;
    __shared__ float red[8];

    int nx = n % IMGq, ny = n / IMGq;
    float w0 = wpos[h], w1 = wpos[Hq + h], w2 = wpos[2 * Hq + h], bb = bpos[h];

    auto logit = [&](int m) {
        float dx = (float)(m % IMGq - nx);
        float dy = (float)(m / IMGq - ny);
        return dx * w0 + dy * w1 + (dx * dx + dy * dy) * w2 + bb;
    };

    float l0 = logit(t);
    float l1 = logit(t + 256);
    float l2 = (t < 64) ? logit(t + 512) : -1e30f;

    float mx = fmaxf(fmaxf(l0, l1), l2);
    #pragma unroll
    for (int o = 16; o; o >>= 1) mx = fmaxf(mx, __shfl_xor_sync(0xFFFFFFFFu, mx, o));
    if ((t & 31) == 0) red[t >> 5] = mx;
    __syncthreads();
    float bm = red[0];
    #pragma unroll
    for (int i = 1; i < 8; ++i) bm = fmaxf(bm, red[i]);
    __syncthreads();

    float e0 = __expf(l0 - bm);
    float e1 = __expf(l1 - bm);
    float e2 = (t < 64) ? __expf(l2 - bm) : 0.0f;
    float s = e0 + e1 + e2;
    #pragma unroll
    for (int o = 16; o; o >>= 1) s += __shfl_xor_sync(0xFFFFFFFFu, s, o);
    if ((t & 31) == 0) red[t >> 5] = s;
    __syncthreads();
    float ts = 0.0f;
    #pragma unroll
    for (int i = 0; i < 8; ++i) ts += red[i];
    float inv = 1.0f / ts;

    float* dst = g_pos + ((size_t)h * Nq + n) * Nq;
    dst[t] = e0 * inv;
    dst[t + 256] = e1 * inv;
    if (t < 64) dst[t + 512] = e2 * inv;
}

// ---------------------------------------------------------------------------
// Pipelined TF32 GEMM, K=32/stage (24 iters) + coalesced staged epilogue.
// A = pre-rounded g_xt (no per-fragment cvt — evidence: R15 alu=28.3%).
// smem: 2*(128*36 + 32*136) floats = 71.7KB -> 2 CTAs/SM.
// ---------------------------------------------------------------------------
#define LDA32 36
#define LDB 136
#define SM_QKV (2 * 128 * LDA32 + 2 * 32 * LDB)

__global__ __launch_bounds__(256, 2) void gemm_qkv_tc(float* __restrict__ dout)
{
    __shared__ float smem_all[SM_QKV];
    float* As0 = smem_all;
    float* Bs0 = smem_all + 2 * 128 * LDA32;

    int tid = threadIdx.x;
    int lane = tid & 31, wid = tid >> 5;
    int g = lane >> 2, t = lane & 3;
    int wm = wid >> 2, wn = wid & 3;

    int row0 = blockIdx.y * 128;
    int col0 = blockIdx.x * 128;

    const float* Bp; int ldb; int cb;
    if (col0 < 1536) { Bp = g_wqkt; ldb = 1536; cb = col0; }
    else             { Bp = g_wvt;  ldb = 768;  cb = col0 - 1536; }

    float acc[4][4][4];
    #pragma unroll
    for (int i = 0; i < 4; ++i)
        #pragma unroll
        for (int j = 0; j < 4; ++j)
            #pragma unroll
            for (int r = 0; r < 4; ++r) acc[i][j][r] = 0.0f;

    auto issue = [&](int kt, int s) {
        int k0 = kt * 32;
        float* Ad = As0 + s * (128 * LDA32);
        float* Bd = Bs0 + s * (32 * LDB);
        #pragma unroll
        for (int r = 0; r < 4; ++r) {
            int c = tid + 256 * r;            // 1024 float4 for A (128x32)
            int row = c >> 3, seg = c & 7;
            cpasync16(&Ad[row * LDA32 + seg * 4],
                      g_xt + (size_t)(row0 + row) * Cq + k0 + seg * 4);
        }
        #pragma unroll
        for (int r = 0; r < 4; ++r) {
            int c = tid + 256 * r;            // 1024 float4 for B (32x128)
            int kr = c >> 5, ns = c & 31;
            cpasync16(&Bd[kr * LDB + ns * 4],
                      Bp + (size_t)(k0 + kr) * ldb + cb + ns * 4);
        }
        CP_COMMIT();
    };

    issue(0, 0);
    for (int kt = 0; kt < 24; ++kt) {
        __syncthreads();
        if (kt + 1 < 24) { issue(kt + 1, (kt + 1) & 1); CP_WAIT1(); }
        else             { CP_WAIT0(); }
        __syncthreads();

        const float* A = As0 + (kt & 1) * (128 * LDA32);
        const float* B = Bs0 + (kt & 1) * (32 * LDB);
        #pragma unroll
        for (int kk = 0; kk < 32; kk += 8) {
            unsigned a[4][4], bf[4][2];
            #pragma unroll
            for (int mf = 0; mf < 4; ++mf) {
                int m = wm * 64 + mf * 16;
                a[mf][0] = __float_as_uint(A[(m + g    ) * LDA32 + kk + t    ]);
                a[mf][1] = __float_as_uint(A[(m + g + 8) * LDA32 + kk + t    ]);
                a[mf][2] = __float_as_uint(A[(m + g    ) * LDA32 + kk + t + 4]);
                a[mf][3] = __float_as_uint(A[(m + g + 8) * LDA32 + kk + t + 4]);
            }
            #pragma unroll
            for (int nf = 0; nf < 4; ++nf) {
                int n = wn * 32 + nf * 8;
                bf[nf][0] = __float_as_uint(B[(kk + t    ) * LDB + n + g]);
                bf[nf][1] = __float_as_uint(B[(kk + t + 4) * LDB + n + g]);
            }
            #pragma unroll
            for (int mf = 0; mf < 4; ++mf)
                #pragma unroll
                for (int nf = 0; nf < 4; ++nf)
                    mma8(acc[mf][nf], a[mf][0], a[mf][1], a[mf][2], a[mf][3],
                         bf[nf][0], bf[nf][1]);
        }
    }

    // ---- coalesced epilogue: stage 128x64 halves, then contiguous stores ----
    bool isQ = (col0 < 768);
    bool isK = (col0 >= 768 && col0 < 1536);
    bool doRound = (col0 < 1536);   // q,k rounded; v exact

    __syncthreads();                 // all smem reads done; reuse as stage
    float* stage = smem_all;         // 128 x 65

    #pragma unroll
    for (int ch = 0; ch < 2; ++ch) {
        if ((wn >> 1) == ch) {
            #pragma unroll
            for (int mf = 0; mf < 4; ++mf)
                #pragma unroll
                for (int nf = 0; nf < 4; ++nf)
                    #pragma unroll
                    for (int ri = 0; ri < 4; ++ri) {
                        int m = wm * 64 + mf * 16 + g + ((ri >> 1) ? 8 : 0);
                        int ccl = (wn & 1) * 32 + nf * 8 + 2 * t + (ri & 1);
                        float val = acc[mf][nf][ri];
                        stage[m * 65 + ccl] = doRound ? f2tff(val) : val;
                    }
        }
        __syncthreads();

        int gnbase = col0 + ch * 64;          // multiple of 64 -> single head
        float* dst;
        if (isQ)      { int hh = gnbase >> 6;          dst = g_q + (size_t)hh * Nq * DHq; }
        else if (isK) { int hh = (gnbase - 768) >> 6;  dst = g_k + (size_t)hh * Nq * DHq; }
        else          { int hh = (gnbase - 1536) >> 6; dst = dout + OFF_V + (size_t)hh * Nq * DHq; }

        #pragma unroll
        for (int i2 = 0; i2 < 32; ++i2) {
            int idx = tid + 256 * i2;          // 0..8191
            int nl = idx >> 6, d = idx & 63;
            int gm = row0 + nl;
            int bi = gm / Nq;
            int n  = gm - bi * Nq;
            dst[((size_t)bi * Hq * Nq + n) * DHq + d] = stage[nl * 65 + d];
        }
        __syncthreads();
    }
}

// ---------------------------------------------------------------------------
// Pipelined projection GEMM, K=32/stage (24 iters): g_ctx @ g_wpt + b_proj
// ---------------------------------------------------------------------------
__global__ __launch_bounds__(256, 2) void gemm_proj_tc(const float* __restrict__ bp,
                                                       float* __restrict__ dout)
{
    __shared__ float As[2][128 * LDA32];
    __shared__ float Bs[2][32 * LDB];

    int tid = threadIdx.x;
    int lane = tid & 31, wid = tid >> 5;
    int g = lane >> 2, t = lane & 3;
    int wm = wid >> 2, wn = wid & 3;

    int row0 = blockIdx.y * 128;
    int col0 = blockIdx.x * 128;

    float acc[4][4][4];
    #pragma unroll
    for (int i = 0; i < 4; ++i)
        #pragma unroll
        for (int j = 0; j < 4; ++j)
            #pragma unroll
            for (int r = 0; r < 4; ++r) acc[i][j][r] = 0.0f;

    auto issue = [&](int kt, int s) {
        int k0 = kt * 32;
        #pragma unroll
        for (int r = 0; r < 4; ++r) {
            int c = tid + 256 * r;
            int row = c >> 3, seg = c & 7;
            cpasync16(&As[s][row * LDA32 + seg * 4],
                      g_ctx + (size_t)(row0 + row) * Cq + k0 + seg * 4);
        }
        #pragma unroll
        for (int r = 0; r < 4; ++r) {
            int c = tid + 256 * r;
            int kr = c >> 5, ns = c & 31;
            cpasync16(&Bs[s][kr * LDB + ns * 4],
                      g_wpt + (size_t)(k0 + kr) * Cq + col0 + ns * 4);
        }
        CP_COMMIT();
    };

    issue(0, 0);
    for (int kt = 0; kt < 24; ++kt) {
        __syncthreads();
        if (kt + 1 < 24) { issue(kt + 1, (kt + 1) & 1); CP_WAIT1(); }
        else             { CP_WAIT0(); }
        __syncthreads();

        const float* A = As[kt & 1];
        const float* B = Bs[kt & 1];
        #pragma unroll
        for (int kk = 0; kk < 32; kk += 8) {
            unsigned a[4][4], bf[4][2];
            #pragma unroll
            for (int mf = 0; mf < 4; ++mf) {
                int m = wm * 64 + mf * 16;
                a[mf][0] = __float_as_uint(A[(m + g    ) * LDA32 + kk + t    ]);
                a[mf][1] = __float_as_uint(A[(m + g + 8) * LDA32 + kk + t    ]);
                a[mf][2] = __float_as_uint(A[(m + g    ) * LDA32 + kk + t + 4]);
                a[mf][3] = __float_as_uint(A[(m + g + 8) * LDA32 + kk + t + 4]);
            }
            #pragma unroll
            for (int nf = 0; nf < 4; ++nf) {
                int n = wn * 32 + nf * 8;
                bf[nf][0] = __float_as_uint(B[(kk + t    ) * LDB + n + g]);
                bf[nf][1] = __float_as_uint(B[(kk + t + 4) * LDB + n + g]);
            }
            #pragma unroll
            for (int mf = 0; mf < 4; ++mf)
                #pragma unroll
                for (int nf = 0; nf < 4; ++nf)
                    mma8(acc[mf][nf], a[mf][0], a[mf][1], a[mf][2], a[mf][3],
                         bf[nf][0], bf[nf][1]);
        }
    }

    #pragma unroll
    for (int mf = 0; mf < 4; ++mf) {
        #pragma unroll
        for (int ri = 0; ri < 4; ++ri) {
            int gm = row0 + wm * 64 + mf * 16 + g + ((ri >> 1) ? 8 : 0);
            #pragma unroll
            for (int nf = 0; nf < 4; ++nf) {
                int gn = col0 + wn * 32 + nf * 8 + 2 * t + (ri & 1);
                dout[(size_t)gm * Cq + gn] = acc[mf][nf][ri] + bp[gn];
            }
        }
    }
}

// ---------------------------------------------------------------------------
// Fused attention v5 (unchanged best): 2 CTAs/SM, 32-row chunks, 3-stage
// single-barrier, Q-frag hoist, no max-pass, V exact from dout.
// smem 110,592 bytes -> 2 CTAs/SM.
// ---------------------------------------------------------------------------
#define LDKV 72
#define SMEM_ATTN_BYTES ((32 * 68 + 3 * 32 * LDKV + 32 * 580) * 4)

__global__ __launch_bounds__(256, 2) void attn_tc(const float* __restrict__ gating,
                                                  float* __restrict__ dout)
{
    extern __shared__ float sm[];
    float* qs  = sm;                              // 32 x 68 (tf32)
    float* kvb = sm + 32 * 68;                    // 3 x 32 x 72
    float* ss  = sm + 32 * 68 + 3 * 32 * LDKV;    // 32 x 580
    __shared__ float spe[32];                     // per-row (1-g)/se

    int tid = threadIdx.x;
    int lane = tid & 31, w = tid >> 5;
    int g = lane >> 2, t = lane & 3;
    int wr2 = w >> 2;
    int wc2 = w & 3;
    int r0 = wr2 * 16;
    int qt = blockIdx.x;
    int h  = blockIdx.y;
    int b  = blockIdx.z;
    int n0 = qt * 32;

    const float* qg = g_q + (((size_t)b * Hq + h) * Nq + n0) * DHq;
    const float* kg = g_k + (((size_t)b * Hq + h) * Nq) * DHq;
    const float* vg = dout + OFF_V + (((size_t)b * Hq + h) * Nq) * DHq;  // exact v

    auto issueKV = [&](const float* src, int kt, int s) {
        float* dst = kvb + s * (32 * LDKV);
        #pragma unroll
        for (int i = 0; i < 2; ++i) {
            int c = tid + 256 * i;
            int row = c >> 4, sg = c & 15;
            cpasync16(&dst[row * LDKV + sg * 4],
                      src + (size_t)kt * 2048 + row * 64 + sg * 4);
        }
        CP_COMMIT();
    };

    issueKV(kg, 0, 0);
    issueKV(kg, 1, 1);

    #pragma unroll
    for (int it = 0; it < 8; ++it) {
        int idx = tid + 256 * it;
        int r = idx >> 6, d = idx & 63;
        qs[r * 68 + d] = qg[idx];
    }
    __syncthreads();

    unsigned qa[8][4];
    #pragma unroll
    for (int k8 = 0; k8 < 8; ++k8) {
        int kk = k8 * 8;
        qa[k8][0] = __float_as_uint(qs[(r0 + g    ) * 68 + kk + t    ]);
        qa[k8][1] = __float_as_uint(qs[(r0 + g + 8) * 68 + kk + t    ]);
        qa[k8][2] = __float_as_uint(qs[(r0 + g    ) * 68 + kk + t + 4]);
        qa[k8][3] = __float_as_uint(qs[(r0 + g + 8) * 68 + kk + t + 4]);
    }

    for (int kt = 0; kt < 18; ++kt) {
        if (kt == 17) CP_WAIT0(); else CP_WAIT1();
        __syncthreads();
        const float* kv = kvb + (kt % 3) * (32 * LDKV);

        float c0[4] = {0.f, 0.f, 0.f, 0.f};
        #pragma unroll
        for (int k8 = 0; k8 < 8; ++k8) {
            int kk = k8 * 8;
            unsigned b0 = __float_as_uint(kv[(wc2 * 8 + g) * LDKV + kk + t]);
            unsigned b1 = __float_as_uint(kv[(wc2 * 8 + g) * LDKV + kk + t + 4]);
            mma8(c0, qa[k8][0], qa[k8][1], qa[k8][2], qa[k8][3], b0, b1);
        }
        int colb = kt * 32 + wc2 * 8 + 2 * t;
        ss[(r0 + g    ) * 580 + colb    ] = c0[0] * 0.125f;
        ss[(r0 + g    ) * 580 + colb + 1] = c0[1] * 0.125f;
        ss[(r0 + g + 8) * 580 + colb    ] = c0[2] * 0.125f;
        ss[(r0 + g + 8) * 580 + colb + 1] = c0[3] * 0.125f;

        if (kt + 2 < 18) issueKV(kg, kt + 2, (kt + 2) % 3);
    }

    issueKV(vg, 0, 0);
    issueKV(vg, 1, 1);
    __syncthreads();

    float gh = gating[h];
    gh = 1.0f / (1.0f + __expf(-gh));

    {
        int r = tid >> 3, c = tid & 7;
        float* row = ss + r * 580;
        float se = 0.0f;
        #pragma unroll 4
        for (int j = 0; j < 72; ++j) {
            int m = c + 8 * j;
            float e = __expf(row[m]);
            row[m] = e;
            se += e;
        }
        #pragma unroll
        for (int o = 4; o; o >>= 1) se += __shfl_xor_sync(0xFFFFFFFFu, se, o);
        if (c == 0) spe[r] = (1.0f - gh) / se;
    }
    __syncthreads();

    {
        float* ao = dout + OFF_ATTN + (((size_t)b * Hq + h) * Nq + n0) * Nq;
        const float* pp = g_pos + ((size_t)h * Nq + n0) * Nq;
        #pragma unroll 4
        for (int it = 0; it < 72; ++it) {
            int idx = tid + 256 * it;
            int rr = idx / 576;
            int mm = idx - rr * 576;
            float val = fmaf(gh, pp[idx], spe[rr] * ss[rr * 580 + mm]);
            ao[idx] = val;
            ss[rr * 580 + mm] = f2tff(val);
        }
    }

    float p0[4] = {0.f, 0.f, 0.f, 0.f};
    float p1[4] = {0.f, 0.f, 0.f, 0.f};
    for (int kt = 0; kt < 18; ++kt) {
        if (kt == 17) CP_WAIT0(); else CP_WAIT1();
        __syncthreads();
        const float* kv = kvb + (kt % 3) * (32 * LDKV);

        #pragma unroll
        for (int kk = 0; kk < 32; kk += 8) {
            int cb = kt * 32 + kk;
            unsigned a0 = __float_as_uint(ss[(r0 + g    ) * 580 + cb + t]);
            unsigned a1 = __float_as_uint(ss[(r0 + g + 8) * 580 + cb + t]);
            unsigned a2 = __float_as_uint(ss[(r0 + g    ) * 580 + cb + t + 4]);
            unsigned a3 = __float_as_uint(ss[(r0 + g + 8) * 580 + cb + t + 4]);
            unsigned b0 = f2tf(kv[(kk + t    ) * LDKV + wc2 * 16 + g]);
            unsigned b1 = f2tf(kv[(kk + t + 4) * LDKV + wc2 * 16 + g]);
            mma8(p0, a0, a1, a2, a3, b0, b1);
            b0 = f2tf(kv[(kk + t    ) * LDKV + wc2 * 16 + 8 + g]);
            b1 = f2tf(kv[(kk + t + 4) * LDKV + wc2 * 16 + 8 + g]);
            mma8(p1, a0, a1, a2, a3, b0, b1);
        }
        if (kt + 2 < 18) issueKV(vg, kt + 2, (kt + 2) % 3);
    }

    {
        size_t bn = (size_t)b * Nq + n0 + r0;
        int d0 = wc2 * 16 + 2 * t;
        size_t hofs = (size_t)h * DHq;
        g_ctx[(bn + g    ) * Cq + hofs + d0    ] = f2tff(p0[0]);
        g_ctx[(bn + g    ) * Cq + hofs + d0 + 1] = f2tff(p0[1]);
        g_ctx[(bn + g + 8) * Cq + hofs + d0    ] = f2tff(p0[2]);
        g_ctx[(bn + g + 8) * Cq + hofs + d0 + 1] = f2tff(p0[3]);
        g_ctx[(bn + g    ) * Cq + hofs + d0 + 8] = f2tff(p1[0]);
        g_ctx[(bn + g    ) * Cq + hofs + d0 + 9] = f2tff(p1[1]);
        g_ctx[(bn + g + 8) * Cq + hofs + d0 + 8] = f2tff(p1[2]);
        g_ctx[(bn + g + 8) * Cq + hofs + d0 + 9] = f2tff(p1[3]);
    }
}

// ---------------------------------------------------------------------------
extern "C" void kernel_launch(void* const* d_in, const int* in_sizes, int n_in,
                              void* d_out, int out_size)
{
    const float* x      = (const float*)d_in[0];
    const float* w_qk   = (const float*)d_in[1];
    const float* w_v    = (const float*)d_in[2];
    const float* w_proj = (const float*)d_in[3];
    const float* b_proj = (const float*)d_in[4];
    const float* w_pos  = (const float*)d_in[5];
    const float* b_pos  = (const float*)d_in[6];
    const float* gating = (const float*)d_in[7];
    float* out = (float*)d_out;

    cudaFuncSetAttribute(attn_tc, cudaFuncAttributeMaxDynamicSharedMemorySize,
                         SMEM_ATTN_BYTES);

    float* d_xt; cudaGetSymbolAddress((void**)&d_xt, g_xt);
    float* d_wqkt; cudaGetSymbolAddress((void**)&d_wqkt, g_wqkt);
    float* d_wvt; cudaGetSymbolAddress((void**)&d_wvt, g_wvt);
    float* d_wpt; cudaGetSymbolAddress((void**)&d_wpt, g_wpt);

    cvt_kernel<<<(7077888 / 4 + 255) / 256, 256>>>(x, d_xt, 7077888 / 4);
    cvt_kernel<<<(1179648 / 4 + 255) / 256, 256>>>(w_qk, d_wqkt, 1179648 / 4);
    cvt2_kernel<<<(589824 / 4 + 255) / 256, 256>>>(w_v, d_wvt, w_proj, d_wpt,
                                                   589824 / 4);
    pos_kernel<<<dim3(Nq, Hq), 256>>>(w_pos, b_pos);
    gemm_qkv_tc<<<dim3(18, 72), 256>>>(out);
    attn_tc<<<dim3(18, Hq, Bq), 256, SMEM_ATTN_BYTES>>>(gating, out);
    gemm_proj_tc<<<dim3(6, 72), 256>>>(b_proj, out);
}

// round 17
// speedup vs baseline: 1.0193x; 1.0193x over previous
#include <cuda_runtime.h>
#include <math.h>

// Problem constants
#define Bq   16
#define Nq   576
#define Cq   768
#define Hq   12
#define DHq  64
#define IMGq 24

// d_out layout (floats): out [B,N,C] | attn [B,H,N,N] | v [B,H,N,Dh]
#define OFF_ATTN 7077888
#define OFF_V    70778880

// Scratch (device globals; allocation-free rule). All *_t hold tf32-rounded fp32.
__device__ float g_wqkt[Cq * 2 * Cq];         // tf32(w_qk)
__device__ float g_wvt[Cq * Cq];              // tf32(w_v)
__device__ float g_wpt[Cq * Cq];              // tf32(w_proj)
__device__ float g_q[Bq * Hq * Nq * DHq];     // tf32(q)  [B,H,N,Dh]
__device__ float g_k[Bq * Hq * Nq * DHq];     // tf32(k)
__device__ float g_ctx[Bq * Nq * Cq];         // tf32(ctx) [B,N,C]
__device__ float g_pos[Hq * Nq * Nq];         // fp32 positional probs [H,N,N]

// ---------------------------------------------------------------------------
__device__ __forceinline__ unsigned f2tf(float f) {
    unsigned u;
    asm("cvt.rna.tf32.f32 %0, %1;" : "=r"(u) : "f"(f));
    return u;
}
__device__ __forceinline__ float f2tff(float f) {
    return __uint_as_float(f2tf(f));
}

__device__ __forceinline__ void mma8(float* c,
                                     unsigned a0, unsigned a1, unsigned a2, unsigned a3,
                                     unsigned b0, unsigned b1)
{
    asm volatile(
        "mma.sync.aligned.m16n8k8.row.col.f32.tf32.tf32.f32 "
        "{%0,%1,%2,%3},{%4,%5,%6,%7},{%8,%9},{%0,%1,%2,%3};\n"
        : "+f"(c[0]), "+f"(c[1]), "+f"(c[2]), "+f"(c[3])
        : "r"(a0), "r"(a1), "r"(a2), "r"(a3), "r"(b0), "r"(b1));
}

__device__ __forceinline__ void cpasync16(void* smem_dst, const void* gmem_src) {
    unsigned s = (unsigned)__cvta_generic_to_shared(smem_dst);
    asm volatile("cp.async.cg.shared.global [%0], [%1], 16;\n" :: "r"(s), "l"(gmem_src));
}
#define CP_COMMIT() asm volatile("cp.async.commit_group;\n" ::: "memory")
#define CP_WAIT1()  asm volatile("cp.async.wait_group 1;\n" ::: "memory")
#define CP_WAIT0()  asm volatile("cp.async.wait_group 0;\n" ::: "memory")

// ---------------------------------------------------------------------------
// Elementwise tf32 rounding pre-pass (float4)
// ---------------------------------------------------------------------------
__global__ __launch_bounds__(256) void cvt_kernel(const float* __restrict__ src,
                                                  float* __restrict__ dst, int n4)
{
    int i = blockIdx.x * 256 + threadIdx.x;
    if (i < n4) {
        float4 v = ((const float4*)src)[i];
        float4 o;
        o.x = f2tff(v.x); o.y = f2tff(v.y); o.z = f2tff(v.z); o.w = f2tff(v.w);
        ((float4*)dst)[i] = o;
    }
}

// Dual-array variant (w_v and w_proj, equal sizes)
__global__ __launch_bounds__(256) void cvt2_kernel(const float* __restrict__ s0,
                                                   float* __restrict__ d0,
                                                   const float* __restrict__ s1,
                                                   float* __restrict__ d1, int n4)
{
    int i = blockIdx.x * 256 + threadIdx.x;
    if (i < n4) {
        float4 v = ((const float4*)s0)[i];
        float4 o;
        o.x = f2tff(v.x); o.y = f2tff(v.y); o.z = f2tff(v.z); o.w = f2tff(v.w);
        ((float4*)d0)[i] = o;
        v = ((const float4*)s1)[i];
        o.x = f2tff(v.x); o.y = f2tff(v.y); o.z = f2tff(v.z); o.w = f2tff(v.w);
        ((float4*)d1)[i] = o;
    }
}

// ---------------------------------------------------------------------------
// Positional scores: softmax over keys of analytic logits
// ---------------------------------------------------------------------------
__global__ __launch_bounds__(256) void pos_kernel(const float* __restrict__ wpos,
                                                  const float* __restrict__ bpos)
{
    int n = blockIdx.x;
    int h = blockIdx.y;
    int t = threadIdx.x;
    __shared__ float red[8];

    int nx = n % IMGq, ny = n / IMGq;
    float w0 = wpos[h], w1 = wpos[Hq + h], w2 = wpos[2 * Hq + h], bb = bpos[h];

    auto logit = [&](int m) {
        float dx = (float)(m % IMGq - nx);
        float dy = (float)(m / IMGq - ny);
        return dx * w0 + dy * w1 + (dx * dx + dy * dy) * w2 + bb;
    };

    float l0 = logit(t);
    float l1 = logit(t + 256);
    float l2 = (t < 64) ? logit(t + 512) : -1e30f;

    float mx = fmaxf(fmaxf(l0, l1), l2);
    #pragma unroll
    for (int o = 16; o; o >>= 1) mx = fmaxf(mx, __shfl_xor_sync(0xFFFFFFFFu, mx, o));
    if ((t & 31) == 0) red[t >> 5] = mx;
    __syncthreads();
    float bm = red[0];
    #pragma unroll
    for (int i = 1; i < 8; ++i) bm = fmaxf(bm, red[i]);
    __syncthreads();

    float e0 = __expf(l0 - bm);
    float e1 = __expf(l1 - bm);
    float e2 = (t < 64) ? __expf(l2 - bm) : 0.0f;
    float s = e0 + e1 + e2;
    #pragma unroll
    for (int o = 16; o; o >>= 1) s += __shfl_xor_sync(0xFFFFFFFFu, s, o);
    if ((t & 31) == 0) red[t >> 5] = s;
    __syncthreads();
    float ts = 0.0f;
    #pragma unroll
    for (int i = 0; i < 8; ++i) ts += red[i];
    float inv = 1.0f / ts;

    float* dst = g_pos + ((size_t)h * Nq + n) * Nq;
    dst[t] = e0 * inv;
    dst[t + 256] = e1 * inv;
    if (t < 64) dst[t + 512] = e2 * inv;
}

// ---------------------------------------------------------------------------
// Pipelined TF32 GEMM, K=32/stage (24 iters) + coalesced staged epilogue.
// A = RAW x; A-fragments tf32-rounded in-register (R15 best; overlapped ALU).
// smem: 2*(128*36 + 32*136) floats = 71.7KB -> 2 CTAs/SM.
// ---------------------------------------------------------------------------
#define LDA32 36
#define LDB 136
#define SM_QKV (2 * 128 * LDA32 + 2 * 32 * LDB)

__global__ __launch_bounds__(256, 2) void gemm_qkv_tc(const float* __restrict__ X,
                                                      float* __restrict__ dout)
{
    __shared__ float smem_all[SM_QKV];
    float* As0 = smem_all;
    float* Bs0 = smem_all + 2 * 128 * LDA32;

    int tid = threadIdx.x;
    int lane = tid & 31, wid = tid >> 5;
    int g = lane >> 2, t = lane & 3;
    int wm = wid >> 2, wn = wid & 3;

    int row0 = blockIdx.y * 128;
    int col0 = blockIdx.x * 128;

    const float* Bp; int ldb; int cb;
    if (col0 < 1536) { Bp = g_wqkt; ldb = 1536; cb = col0; }
    else             { Bp = g_wvt;  ldb = 768;  cb = col0 - 1536; }

    float acc[4][4][4];
    #pragma unroll
    for (int i = 0; i < 4; ++i)
        #pragma unroll
        for (int j = 0; j < 4; ++j)
            #pragma unroll
            for (int r = 0; r < 4; ++r) acc[i][j][r] = 0.0f;

    auto issue = [&](int kt, int s) {
        int k0 = kt * 32;
        float* Ad = As0 + s * (128 * LDA32);
        float* Bd = Bs0 + s * (32 * LDB);
        #pragma unroll
        for (int r = 0; r < 4; ++r) {
            int c = tid + 256 * r;            // 1024 float4 for A (128x32)
            int row = c >> 3, seg = c & 7;
            cpasync16(&Ad[row * LDA32 + seg * 4],
                      X + (size_t)(row0 + row) * Cq + k0 + seg * 4);
        }
        #pragma unroll
        for (int r = 0; r < 4; ++r) {
            int c = tid + 256 * r;            // 1024 float4 for B (32x128)
            int kr = c >> 5, ns = c & 31;
            cpasync16(&Bd[kr * LDB + ns * 4],
                      Bp + (size_t)(k0 + kr) * ldb + cb + ns * 4);
        }
        CP_COMMIT();
    };

    issue(0, 0);
    for (int kt = 0; kt < 24; ++kt) {
        __syncthreads();
        if (kt + 1 < 24) { issue(kt + 1, (kt + 1) & 1); CP_WAIT1(); }
        else             { CP_WAIT0(); }
        __syncthreads();

        const float* A = As0 + (kt & 1) * (128 * LDA32);
        const float* B = Bs0 + (kt & 1) * (32 * LDB);
        #pragma unroll
        for (int kk = 0; kk < 32; kk += 8) {
            unsigned a[4][4], bf[4][2];
            #pragma unroll
            for (int mf = 0; mf < 4; ++mf) {
                int m = wm * 64 + mf * 16;
                a[mf][0] = f2tf(A[(m + g    ) * LDA32 + kk + t    ]);
                a[mf][1] = f2tf(A[(m + g + 8) * LDA32 + kk + t    ]);
                a[mf][2] = f2tf(A[(m + g    ) * LDA32 + kk + t + 4]);
                a[mf][3] = f2tf(A[(m + g + 8) * LDA32 + kk + t + 4]);
            }
            #pragma unroll
            for (int nf = 0; nf < 4; ++nf) {
                int n = wn * 32 + nf * 8;
                bf[nf][0] = __float_as_uint(B[(kk + t    ) * LDB + n + g]);
                bf[nf][1] = __float_as_uint(B[(kk + t + 4) * LDB + n + g]);
            }
            #pragma unroll
            for (int mf = 0; mf < 4; ++mf)
                #pragma unroll
                for (int nf = 0; nf < 4; ++nf)
                    mma8(acc[mf][nf], a[mf][0], a[mf][1], a[mf][2], a[mf][3],
                         bf[nf][0], bf[nf][1]);
        }
    }

    // ---- coalesced epilogue: stage 128x64 halves, then contiguous stores ----
    bool isQ = (col0 < 768);
    bool isK = (col0 >= 768 && col0 < 1536);
    bool doRound = (col0 < 1536);   // q,k rounded; v exact

    __syncthreads();                 // all smem reads done; reuse as stage
    float* stage = smem_all;         // 128 x 65

    #pragma unroll
    for (int ch = 0; ch < 2; ++ch) {
        if ((wn >> 1) == ch) {
            #pragma unroll
            for (int mf = 0; mf < 4; ++mf)
                #pragma unroll
                for (int nf = 0; nf < 4; ++nf)
                    #pragma unroll
                    for (int ri = 0; ri < 4; ++ri) {
                        int m = wm * 64 + mf * 16 + g + ((ri >> 1) ? 8 : 0);
                        int ccl = (wn & 1) * 32 + nf * 8 + 2 * t + (ri & 1);
                        float val = acc[mf][nf][ri];
                        stage[m * 65 + ccl] = doRound ? f2tff(val) : val;
                    }
        }
        __syncthreads();

        int gnbase = col0 + ch * 64;          // multiple of 64 -> single head
        float* dst;
        if (isQ)      { int hh = gnbase >> 6;          dst = g_q + (size_t)hh * Nq * DHq; }
        else if (isK) { int hh = (gnbase - 768) >> 6;  dst = g_k + (size_t)hh * Nq * DHq; }
        else          { int hh = (gnbase - 1536) >> 6; dst = dout + OFF_V + (size_t)hh * Nq * DHq; }

        #pragma unroll
        for (int i2 = 0; i2 < 32; ++i2) {
            int idx = tid + 256 * i2;          // 0..8191
            int nl = idx >> 6, d = idx & 63;
            int gm = row0 + nl;
            int bi = gm / Nq;
            int n  = gm - bi * Nq;
            dst[((size_t)bi * Hq * Nq + n) * DHq + d] = stage[nl * 65 + d];
        }
        __syncthreads();
    }
}

// ---------------------------------------------------------------------------
// Pipelined projection GEMM, K=32/stage (24 iters): g_ctx @ g_wpt + b_proj
// ---------------------------------------------------------------------------
__global__ __launch_bounds__(256, 2) void gemm_proj_tc(const float* __restrict__ bp,
                                                       float* __restrict__ dout)
{
    __shared__ float As[2][128 * LDA32];
    __shared__ float Bs[2][32 * LDB];

    int tid = threadIdx.x;
    int lane = tid & 31, wid = tid >> 5;
    int g = lane >> 2, t = lane & 3;
    int wm = wid >> 2, wn = wid & 3;

    int row0 = blockIdx.y * 128;
    int col0 = blockIdx.x * 128;

    float acc[4][4][4];
    #pragma unroll
    for (int i = 0; i < 4; ++i)
        #pragma unroll
        for (int j = 0; j < 4; ++j)
            #pragma unroll
            for (int r = 0; r < 4; ++r) acc[i][j][r] = 0.0f;

    auto issue = [&](int kt, int s) {
        int k0 = kt * 32;
        #pragma unroll
        for (int r = 0; r < 4; ++r) {
            int c = tid + 256 * r;
            int row = c >> 3, seg = c & 7;
            cpasync16(&As[s][row * LDA32 + seg * 4],
                      g_ctx + (size_t)(row0 + row) * Cq + k0 + seg * 4);
        }
        #pragma unroll
        for (int r = 0; r < 4; ++r) {
            int c = tid + 256 * r;
            int kr = c >> 5, ns = c & 31;
            cpasync16(&Bs[s][kr * LDB + ns * 4],
                      g_wpt + (size_t)(k0 + kr) * Cq + col0 + ns * 4);
        }
        CP_COMMIT();
    };

    issue(0, 0);
    for (int kt = 0; kt < 24; ++kt) {
        __syncthreads();
        if (kt + 1 < 24) { issue(kt + 1, (kt + 1) & 1); CP_WAIT1(); }
        else             { CP_WAIT0(); }
        __syncthreads();

        const float* A = As[kt & 1];
        const float* B = Bs[kt & 1];
        #pragma unroll
        for (int kk = 0; kk < 32; kk += 8) {
            unsigned a[4][4], bf[4][2];
            #pragma unroll
            for (int mf = 0; mf < 4; ++mf) {
                int m = wm * 64 + mf * 16;
                a[mf][0] = __float_as_uint(A[(m + g    ) * LDA32 + kk + t    ]);
                a[mf][1] = __float_as_uint(A[(m + g + 8) * LDA32 + kk + t    ]);
                a[mf][2] = __float_as_uint(A[(m + g    ) * LDA32 + kk + t + 4]);
                a[mf][3] = __float_as_uint(A[(m + g + 8) * LDA32 + kk + t + 4]);
            }
            #pragma unroll
            for (int nf = 0; nf < 4; ++nf) {
                int n = wn * 32 + nf * 8;
                bf[nf][0] = __float_as_uint(B[(kk + t    ) * LDB + n + g]);
                bf[nf][1] = __float_as_uint(B[(kk + t + 4) * LDB + n + g]);
            }
            #pragma unroll
            for (int mf = 0; mf < 4; ++mf)
                #pragma unroll
                for (int nf = 0; nf < 4; ++nf)
                    mma8(acc[mf][nf], a[mf][0], a[mf][1], a[mf][2], a[mf][3],
                         bf[nf][0], bf[nf][1]);
        }
    }

    #pragma unroll
    for (int mf = 0; mf < 4; ++mf) {
        #pragma unroll
        for (int ri = 0; ri < 4; ++ri) {
            int gm = row0 + wm * 64 + mf * 16 + g + ((ri >> 1) ? 8 : 0);
            #pragma unroll
            for (int nf = 0; nf < 4; ++nf) {
                int gn = col0 + wn * 32 + nf * 8 + 2 * t + (ri & 1);
                dout[(size_t)gm * Cq + gn] = acc[mf][nf][ri] + bp[gn];
            }
        }
    }
}

// ---------------------------------------------------------------------------
// Fused attention v6: v5 + issue(kt+2) moved BEFORE the chunk's mma work
// (stage (kt+2)%3 is provably free right after the iteration-kt barrier).
// smem 110,592 bytes -> 2 CTAs/SM.
// ---------------------------------------------------------------------------
#define LDKV 72
#define SMEM_ATTN_BYTES ((32 * 68 + 3 * 32 * LDKV + 32 * 580) * 4)

__global__ __launch_bounds__(256, 2) void attn_tc(const float* __restrict__ gating,
                                                  float* __restrict__ dout)
{
    extern __shared__ float sm[];
    float* qs  = sm;                              // 32 x 68 (tf32)
    float* kvb = sm + 32 * 68;                    // 3 x 32 x 72
    float* ss  = sm + 32 * 68 + 3 * 32 * LDKV;    // 32 x 580
    __shared__ float spe[32];                     // per-row (1-g)/se

    int tid = threadIdx.x;
    int lane = tid & 31, w = tid >> 5;
    int g = lane >> 2, t = lane & 3;
    int wr2 = w >> 2;
    int wc2 = w & 3;
    int r0 = wr2 * 16;
    int qt = blockIdx.x;
    int h  = blockIdx.y;
    int b  = blockIdx.z;
    int n0 = qt * 32;

    const float* qg = g_q + (((size_t)b * Hq + h) * Nq + n0) * DHq;
    const float* kg = g_k + (((size_t)b * Hq + h) * Nq) * DHq;
    const float* vg = dout + OFF_V + (((size_t)b * Hq + h) * Nq) * DHq;  // exact v

    auto issueKV = [&](const float* src, int kt, int s) {
        float* dst = kvb + s * (32 * LDKV);
        #pragma unroll
        for (int i = 0; i < 2; ++i) {
            int c = tid + 256 * i;
            int row = c >> 4, sg = c & 15;
            cpasync16(&dst[row * LDKV + sg * 4],
                      src + (size_t)kt * 2048 + row * 64 + sg * 4);
        }
        CP_COMMIT();
    };

    issueKV(kg, 0, 0);
    issueKV(kg, 1, 1);

    #pragma unroll
    for (int it = 0; it < 8; ++it) {
        int idx = tid + 256 * it;
        int r = idx >> 6, d = idx & 63;
        qs[r * 68 + d] = qg[idx];
    }
    __syncthreads();

    unsigned qa[8][4];
    #pragma unroll
    for (int k8 = 0; k8 < 8; ++k8) {
        int kk = k8 * 8;
        qa[k8][0] = __float_as_uint(qs[(r0 + g    ) * 68 + kk + t    ]);
        qa[k8][1] = __float_as_uint(qs[(r0 + g + 8) * 68 + kk + t    ]);
        qa[k8][2] = __float_as_uint(qs[(r0 + g    ) * 68 + kk + t + 4]);
        qa[k8][3] = __float_as_uint(qs[(r0 + g + 8) * 68 + kk + t + 4]);
    }

    // ---- scores: issue(kt+2) right after the barrier (stage provably free) ----
    for (int kt = 0; kt < 18; ++kt) {
        if (kt == 17) CP_WAIT0(); else CP_WAIT1();
        __syncthreads();
        if (kt + 2 < 18) issueKV(kg, kt + 2, (kt + 2) % 3);
        const float* kv = kvb + (kt % 3) * (32 * LDKV);

        float c0[4] = {0.f, 0.f, 0.f, 0.f};
        #pragma unroll
        for (int k8 = 0; k8 < 8; ++k8) {
            int kk = k8 * 8;
            unsigned b0 = __float_as_uint(kv[(wc2 * 8 + g) * LDKV + kk + t]);
            unsigned b1 = __float_as_uint(kv[(wc2 * 8 + g) * LDKV + kk + t + 4]);
            mma8(c0, qa[k8][0], qa[k8][1], qa[k8][2], qa[k8][3], b0, b1);
        }
        int colb = kt * 32 + wc2 * 8 + 2 * t;
        ss[(r0 + g    ) * 580 + colb    ] = c0[0] * 0.125f;
        ss[(r0 + g    ) * 580 + colb + 1] = c0[1] * 0.125f;
        ss[(r0 + g + 8) * 580 + colb    ] = c0[2] * 0.125f;
        ss[(r0 + g + 8) * 580 + colb + 1] = c0[3] * 0.125f;
    }

    issueKV(vg, 0, 0);
    issueKV(vg, 1, 1);
    __syncthreads();

    float gh = gating[h];
    gh = 1.0f / (1.0f + __expf(-gh));

    {
        int r = tid >> 3, c = tid & 7;
        float* row = ss + r * 580;
        float se = 0.0f;
        #pragma unroll 4
        for (int j = 0; j < 72; ++j) {
            int m = c + 8 * j;
            float e = __expf(row[m]);
            row[m] = e;
            se += e;
        }
        #pragma unroll
        for (int o = 4; o; o >>= 1) se += __shfl_xor_sync(0xFFFFFFFFu, se, o);
        if (c == 0) spe[r] = (1.0f - gh) / se;
    }
    __syncthreads();

    {
        float* ao = dout + OFF_ATTN + (((size_t)b * Hq + h) * Nq + n0) * Nq;
        const float* pp = g_pos + ((size_t)h * Nq + n0) * Nq;
        #pragma unroll 4
        for (int it = 0; it < 72; ++it) {
            int idx = tid + 256 * it;
            int rr = idx / 576;
            int mm = idx - rr * 576;
            float val = fmaf(gh, pp[idx], spe[rr] * ss[rr * 580 + mm]);
            ao[idx] = val;
            ss[rr * 580 + mm] = f2tff(val);
        }
    }

    // ---- ctx = P @ V : issue(kt+2) right after the barrier ----
    float p0[4] = {0.f, 0.f, 0.f, 0.f};
    float p1[4] = {0.f, 0.f, 0.f, 0.f};
    for (int kt = 0; kt < 18; ++kt) {
        if (kt == 17) CP_WAIT0(); else CP_WAIT1();
        __syncthreads();
        if (kt + 2 < 18) issueKV(vg, kt + 2, (kt + 2) % 3);
        const float* kv = kvb + (kt % 3) * (32 * LDKV);

        #pragma unroll
        for (int kk = 0; kk < 32; kk += 8) {
            int cb = kt * 32 + kk;
            unsigned a0 = __float_as_uint(ss[(r0 + g    ) * 580 + cb + t]);
            unsigned a1 = __float_as_uint(ss[(r0 + g + 8) * 580 + cb + t]);
            unsigned a2 = __float_as_uint(ss[(r0 + g    ) * 580 + cb + t + 4]);
            unsigned a3 = __float_as_uint(ss[(r0 + g + 8) * 580 + cb + t + 4]);
            unsigned b0 = f2tf(kv[(kk + t    ) * LDKV + wc2 * 16 + g]);
            unsigned b1 = f2tf(kv[(kk + t + 4) * LDKV + wc2 * 16 + g]);
            mma8(p0, a0, a1, a2, a3, b0, b1);
            b0 = f2tf(kv[(kk + t    ) * LDKV + wc2 * 16 + 8 + g]);
            b1 = f2tf(kv[(kk + t + 4) * LDKV + wc2 * 16 + 8 + g]);
            mma8(p1, a0, a1, a2, a3, b0, b1);
        }
    }

    {
        size_t bn = (size_t)b * Nq + n0 + r0;
        int d0 = wc2 * 16 + 2 * t;
        size_t hofs = (size_t)h * DHq;
        g_ctx[(bn + g    ) * Cq + hofs + d0    ] = f2tff(p0[0]);
        g_ctx[(bn + g    ) * Cq + hofs + d0 + 1] = f2tff(p0[1]);
        g_ctx[(bn + g + 8) * Cq + hofs + d0    ] = f2tff(p0[2]);
        g_ctx[(bn + g + 8) * Cq + hofs + d0 + 1] = f2tff(p0[3]);
        g_ctx[(bn + g    ) * Cq + hofs + d0 + 8] = f2tff(p1[0]);
        g_ctx[(bn + g    ) * Cq + hofs + d0 + 9] = f2tff(p1[1]);
        g_ctx[(bn + g + 8) * Cq + hofs + d0 + 8] = f2tff(p1[2]);
        g_ctx[(bn + g + 8) * Cq + hofs + d0 + 9] = f2tff(p1[3]);
    }
}

// ---------------------------------------------------------------------------
extern "C" void kernel_launch(void* const* d_in, const int* in_sizes, int n_in,
                              void* d_out, int out_size)
{
    const float* x      = (const float*)d_in[0];
    const float* w_qk   = (const float*)d_in[1];
    const float* w_v    = (const float*)d_in[2];
    const float* w_proj = (const float*)d_in[3];
    const float* b_proj = (const float*)d_in[4];
    const float* w_pos  = (const float*)d_in[5];
    const float* b_pos  = (const float*)d_in[6];
    const float* gating = (const float*)d_in[7];
    float* out = (float*)d_out;

    cudaFuncSetAttribute(attn_tc, cudaFuncAttributeMaxDynamicSharedMemorySize,
                         SMEM_ATTN_BYTES);

    float* d_wqkt; cudaGetSymbolAddress((void**)&d_wqkt, g_wqkt);
    float* d_wvt; cudaGetSymbolAddress((void**)&d_wvt, g_wvt);
    float* d_wpt; cudaGetSymbolAddress((void**)&d_wpt, g_wpt);

    cvt_kernel<<<(1179648 / 4 + 255) / 256, 256>>>(w_qk, d_wqkt, 1179648 / 4);
    cvt2_kernel<<<(589824 / 4 + 255) / 256, 256>>>(w_v, d_wvt, w_proj, d_wpt,
                                                   589824 / 4);
    pos_kernel<<<dim3(Nq, Hq), 256>>>(w_pos, b_pos);
    gemm_qkv_tc<<<dim3(18, 72), 256>>>(x, out);
    attn_tc<<<dim3(18, Hq, Bq), 256, SMEM_ATTN_BYTES>>>(gating, out);
    gemm_proj_tc<<<dim3(6, 72), 256>>>(b_proj, out);
}